// round 6
// baseline (speedup 1.0000x reference)
#include <cuda_runtime.h>
#include <cuda_fp16.h>
#include <math.h>
#include <stdint.h>

#define Bsz 2
#define Tsz 2048
#define Csz 1024
#define Hn  16
#define HDd 64

// Scratch
__device__ float  g_qkv[Bsz * Tsz * 3 * Csz];
__device__ __half g_qh[Bsz * Hn * Tsz * HDd];
__device__ __half g_kh[Bsz * Hn * Tsz * HDd];
__device__ __half g_vh[Bsz * Hn * Tsz * HDd];
__device__ float  g_y[Bsz * Tsz * Csz];

// ===========================================================================
// Helpers
// ===========================================================================
__device__ __forceinline__ uint32_t smem_u32(const void* p) {
    uint32_t a;
    asm("{ .reg .u64 t; cvta.to.shared.u64 t, %1; cvt.u32.u64 %0, t; }"
        : "=r"(a) : "l"(p));
    return a;
}

#define LDSM4(r0, r1, r2, r3, ad)                                              \
    asm volatile("ldmatrix.sync.aligned.m8n8.x4.shared.b16 {%0,%1,%2,%3}, [%4];" \
                 : "=r"(r0), "=r"(r1), "=r"(r2), "=r"(r3) : "r"(ad))

#define LDSM4T(r0, r1, r2, r3, ad)                                             \
    asm volatile("ldmatrix.sync.aligned.m8n8.x4.trans.shared.b16 {%0,%1,%2,%3}, [%4];" \
                 : "=r"(r0), "=r"(r1), "=r"(r2), "=r"(r3) : "r"(ad))

#define MMA16816(d, a, b0, b1)                                                 \
    asm volatile("mma.sync.aligned.m16n8k16.row.col.f32.f16.f16.f32 "          \
                 "{%0,%1,%2,%3}, {%4,%5,%6,%7}, {%8,%9}, {%0,%1,%2,%3};"       \
                 : "+f"((d)[0]), "+f"((d)[1]), "+f"((d)[2]), "+f"((d)[3])      \
                 : "r"((a)[0]), "r"((a)[1]), "r"((a)[2]), "r"((a)[3]),         \
                   "r"(b0), "r"(b1))

__device__ __forceinline__ float ex2f(float x) {
    float y;
    asm("ex2.approx.f32 %0, %1;" : "=f"(y) : "f"(x));
    return y;
}
__device__ __forceinline__ uint32_t packh2(float hi, float lo) {
    uint32_t r;
    asm("cvt.rn.f16x2.f32 %0, %1, %2;" : "=r"(r) : "f"(hi), "f"(lo));
    return r;
}

// ===========================================================================
// SGEMM (fp32): 128x128 tile, 8x8 micro (unchanged)
// ===========================================================================
__global__ __launch_bounds__(256, 2)
void sgemm128(const float* __restrict__ A,
              const float* __restrict__ Bm,
              const float* __restrict__ bias,
              float* __restrict__ Cm,
              int M, int N, int K) {
    __shared__ float As[16][132];
    __shared__ float Bs[16][132];

    const int tid = threadIdx.x;
    const int tx = tid & 15;
    const int ty = tid >> 4;
    const int m0 = blockIdx.y * 128;
    const int n0 = blockIdx.x * 128;

    float acc[8][8] = {};

    for (int k0 = 0; k0 < K; k0 += 16) {
        #pragma unroll
        for (int i = 0; i < 2; i++) {
            const int idx = tid + i * 256;
            const int row = idx >> 2;
            const int c4  = idx & 3;
            float4 a = *(const float4*)&A[(size_t)(m0 + row) * K + k0 + c4 * 4];
            As[c4 * 4 + 0][row] = a.x;
            As[c4 * 4 + 1][row] = a.y;
            As[c4 * 4 + 2][row] = a.z;
            As[c4 * 4 + 3][row] = a.w;
        }
        #pragma unroll
        for (int i = 0; i < 2; i++) {
            const int idx = tid + i * 256;
            const int br  = idx >> 5;
            const int bc4 = idx & 31;
            *(float4*)&Bs[br][bc4 * 4] =
                *(const float4*)&Bm[(size_t)(k0 + br) * N + n0 + bc4 * 4];
        }
        __syncthreads();

        #pragma unroll
        for (int kk = 0; kk < 16; kk++) {
            float av[8], bv[8];
            float4 a0 = *(const float4*)&As[kk][ty * 8];
            float4 a1 = *(const float4*)&As[kk][ty * 8 + 4];
            float4 b0 = *(const float4*)&Bs[kk][tx * 8];
            float4 b1 = *(const float4*)&Bs[kk][tx * 8 + 4];
            av[0]=a0.x; av[1]=a0.y; av[2]=a0.z; av[3]=a0.w;
            av[4]=a1.x; av[5]=a1.y; av[6]=a1.z; av[7]=a1.w;
            bv[0]=b0.x; bv[1]=b0.y; bv[2]=b0.z; bv[3]=b0.w;
            bv[4]=b1.x; bv[5]=b1.y; bv[6]=b1.z; bv[7]=b1.w;
            #pragma unroll
            for (int i = 0; i < 8; i++)
                #pragma unroll
                for (int j = 0; j < 8; j++)
                    acc[i][j] += av[i] * bv[j];
        }
        __syncthreads();
    }

    float4 bb0 = *(const float4*)&bias[n0 + tx * 8];
    float4 bb1 = *(const float4*)&bias[n0 + tx * 8 + 4];
    float bv[8] = {bb0.x, bb0.y, bb0.z, bb0.w, bb1.x, bb1.y, bb1.z, bb1.w};
    #pragma unroll
    for (int i = 0; i < 8; i++) {
        float4 o0, o1;
        o0.x = acc[i][0] + bv[0]; o0.y = acc[i][1] + bv[1];
        o0.z = acc[i][2] + bv[2]; o0.w = acc[i][3] + bv[3];
        o1.x = acc[i][4] + bv[4]; o1.y = acc[i][5] + bv[5];
        o1.z = acc[i][6] + bv[6]; o1.w = acc[i][7] + bv[7];
        float* cp = &Cm[(size_t)(m0 + ty * 8 + i) * N + n0 + tx * 8];
        *(float4*)cp = o0;
        *(float4*)(cp + 4) = o1;
    }
}

// ===========================================================================
// RoPE + split + transpose, output fp16: g_qkv -> g_qh/g_kh (rope'd), g_vh
// ===========================================================================
__global__ void rope_split_kernel(const float* __restrict__ qkv) {
    const int idx = blockIdx.x * blockDim.x + threadIdx.x;
    const int d2 = idx & 31;
    const int h  = (idx >> 5) & 15;
    const int t  = (idx >> 9) & 2047;
    const int b  = idx >> 20;

    const float* base = qkv + (size_t)(b * Tsz + t) * (3 * Csz);
    const int off = h * HDd + d2;

    const float qf = base[off],           qs = base[off + 32];
    const float kf = base[Csz + off],     ks = base[Csz + off + 32];
    const float vf = base[2 * Csz + off], vs = base[2 * Csz + off + 32];

    const float inv_ts = powf(10000.0f, -(float)d2 * (1.0f / 32.0f));
    const float ang = (float)t * inv_ts;
    float sn, cs;
    sincosf(ang, &sn, &cs);

    const size_t o = (size_t)((b * Hn + h) * Tsz + t) * HDd + d2;
    g_qh[o]      = __float2half_rn(qf * cs - qs * sn);
    g_qh[o + 32] = __float2half_rn(qs * cs + qf * sn);
    g_kh[o]      = __float2half_rn(kf * cs - ks * sn);
    g_kh[o + 32] = __float2half_rn(ks * cs + kf * sn);
    g_vh[o]      = __float2half_rn(vf);
    g_vh[o + 32] = __float2half_rn(vs);
}

// ===========================================================================
// Flash attention via mma.sync (fp16 in, fp32 accum), FA2 layout.
// 256 threads / 8 warps; Q tile 128 rows (16/warp), KV tile 64.
// fp16 global Q/K/V; smem tiles swizzled, copied as raw 16B chunks.
// __launch_bounds__(256,1): no register cap -> no spills.
// ===========================================================================
#define SCALE_L2E 0.1803368801111244f   // 0.125 * log2(e)

__global__ __launch_bounds__(256, 1)
void flash_mma(const __half* __restrict__ Q,
               const __half* __restrict__ K,
               const __half* __restrict__ V,
               float* __restrict__ Y) {
    __shared__ char smem[49152];
    char* Qs = smem;                              // 16 KB
    char* Kb0 = smem + 16384;                     // 8 KB each
    char* Kb1 = smem + 24576;
    char* Vb0 = smem + 32768;
    char* Vb1 = smem + 40960;

    const int tid  = threadIdx.x;
    const int wid  = tid >> 5;
    const int lane = tid & 31;
    const int g = lane >> 2;       // row-in-group
    const int t = lane & 3;        // col pair selector

    const int qt = gridDim.x - 1 - blockIdx.x;    // long blocks first
    const int h  = blockIdx.y;
    const int b  = blockIdx.z;
    const size_t bh = (size_t)(b * Hn + h) * Tsz;
    const int qbase = qt * 128 + wid * 16;
    const int row_lo = qbase + g;
    const int row_hi = row_lo + 8;

    // --- Load Q tile: 128 rows x 8 chunks(16B), swizzled copy ---
    #pragma unroll
    for (int i = 0; i < 4; i++) {
        const int idx = tid + i * 256;     // 0..1023
        const int r = idx >> 3;            // 0..127
        const int c = idx & 7;             // 16B chunk
        uint4 q = *(const uint4*)&Q[(bh + qt * 128 + r) * HDd + c * 8];
        *(uint4*)(Qs + r * 128 + ((c ^ (r & 7)) << 4)) = q;
    }
    // --- Preload K/V tile 0: 64 rows x 8 chunks each ---
    #pragma unroll
    for (int i = 0; i < 2; i++) {
        const int idx = tid + i * 256;     // 0..511
        const int r = idx >> 3;            // 0..63
        const int c = idx & 7;
        uint4 kk = *(const uint4*)&K[(bh + r) * HDd + c * 8];
        *(uint4*)(Kb0 + r * 128 + ((c ^ (r & 7)) << 4)) = kk;
        uint4 vv = *(const uint4*)&V[(bh + r) * HDd + c * 8];
        *(uint4*)(Vb0 + r * 128 + ((c ^ (r & 7)) << 4)) = vv;
    }
    __syncthreads();

    // --- Q fragments (persistent): qf[ktile][4] ---
    uint32_t qf[4][4];
    {
        const uint32_t sQ = smem_u32(Qs);
        const int mat = lane >> 3;
        const int qr  = wid * 16 + (lane & 7) + ((mat & 1) << 3);
        #pragma unroll
        for (int k = 0; k < 4; k++) {
            const int chunk = 2 * k + (mat >> 1);
            const uint32_t ad = sQ + qr * 128 + (((chunk ^ (qr & 7))) << 4);
            LDSM4(qf[k][0], qf[k][1], qf[k][2], qf[k][3], ad);
        }
    }

    float oacc[8][4] = {};
    float mst[2] = {-1e30f, -1e30f};
    float lst[2] = {0.0f, 0.0f};

    const int nkt = 2 * qt + 2;
    for (int kt = 0; kt < nkt; kt++) {
        char* Kc = (kt & 1) ? Kb1 : Kb0;
        char* Vc = (kt & 1) ? Vb1 : Vb0;

        // Prefetch next K/V into the other buffer (raw swizzled copy)
        if (kt + 1 < nkt) {
            char* Kn = (kt & 1) ? Kb0 : Kb1;
            char* Vn = (kt & 1) ? Vb0 : Vb1;
            const size_t base = bh + (size_t)(kt + 1) * 64;
            #pragma unroll
            for (int i = 0; i < 2; i++) {
                const int idx = tid + i * 256;
                const int r = idx >> 3;
                const int c = idx & 7;
                uint4 kk = *(const uint4*)&K[(base + r) * HDd + c * 8];
                *(uint4*)(Kn + r * 128 + ((c ^ (r & 7)) << 4)) = kk;
                uint4 vv = *(const uint4*)&V[(base + r) * HDd + c * 8];
                *(uint4*)(Vn + r * 128 + ((c ^ (r & 7)) << 4)) = vv;
            }
        }

        // --- GEMM1: S = Q @ K^T ---
        float sacc[8][4] = {};
        {
            const uint32_t sK = smem_u32(Kc);
            const int kr = lane & 7;
            #pragma unroll
            for (int n = 0; n < 8; n++) {
                const int row = n * 8 + kr;
                const int c0  = lane >> 3;
                uint32_t kb[8];
                const uint32_t rb = sK + row * 128;
                LDSM4(kb[0], kb[1], kb[2], kb[3],
                      rb + (((c0 ^ (row & 7))) << 4));
                LDSM4(kb[4], kb[5], kb[6], kb[7],
                      rb + ((((c0 + 4) ^ (row & 7))) << 4));
                #pragma unroll
                for (int k = 0; k < 4; k++)
                    MMA16816(sacc[n], qf[k], kb[2 * k], kb[2 * k + 1]);
            }
        }

        // --- Softmax (log2 domain, mask, online update) ---
        const bool dotest = (kt * 64 + 63) > qbase;
        float rmx_lo = -1e30f, rmx_hi = -1e30f;
        #pragma unroll
        for (int n = 0; n < 8; n++) {
            #pragma unroll
            for (int j = 0; j < 4; j++) sacc[n][j] *= SCALE_L2E;
            if (dotest) {
                const int cb = kt * 64 + n * 8 + 2 * t;
                if (cb     > row_lo) sacc[n][0] = -1e30f;
                if (cb + 1 > row_lo) sacc[n][1] = -1e30f;
                if (cb     > row_hi) sacc[n][2] = -1e30f;
                if (cb + 1 > row_hi) sacc[n][3] = -1e30f;
            }
            rmx_lo = fmaxf(rmx_lo, fmaxf(sacc[n][0], sacc[n][1]));
            rmx_hi = fmaxf(rmx_hi, fmaxf(sacc[n][2], sacc[n][3]));
        }
        rmx_lo = fmaxf(rmx_lo, __shfl_xor_sync(0xffffffffu, rmx_lo, 1));
        rmx_lo = fmaxf(rmx_lo, __shfl_xor_sync(0xffffffffu, rmx_lo, 2));
        rmx_hi = fmaxf(rmx_hi, __shfl_xor_sync(0xffffffffu, rmx_hi, 1));
        rmx_hi = fmaxf(rmx_hi, __shfl_xor_sync(0xffffffffu, rmx_hi, 2));

        const float mn_lo = fmaxf(mst[0], rmx_lo);
        const float mn_hi = fmaxf(mst[1], rmx_hi);
        const float corr_lo = ex2f(mst[0] - mn_lo);
        const float corr_hi = ex2f(mst[1] - mn_hi);
        mst[0] = mn_lo; mst[1] = mn_hi;

        float sum_lo = 0.0f, sum_hi = 0.0f;
        #pragma unroll
        for (int n = 0; n < 8; n++) {
            sacc[n][0] = ex2f(sacc[n][0] - mn_lo);
            sacc[n][1] = ex2f(sacc[n][1] - mn_lo);
            sacc[n][2] = ex2f(sacc[n][2] - mn_hi);
            sacc[n][3] = ex2f(sacc[n][3] - mn_hi);
            sum_lo += sacc[n][0] + sacc[n][1];
            sum_hi += sacc[n][2] + sacc[n][3];
        }
        sum_lo += __shfl_xor_sync(0xffffffffu, sum_lo, 1);
        sum_lo += __shfl_xor_sync(0xffffffffu, sum_lo, 2);
        sum_hi += __shfl_xor_sync(0xffffffffu, sum_hi, 1);
        sum_hi += __shfl_xor_sync(0xffffffffu, sum_hi, 2);
        lst[0] = lst[0] * corr_lo + sum_lo;
        lst[1] = lst[1] * corr_hi + sum_hi;

        #pragma unroll
        for (int n = 0; n < 8; n++) {
            oacc[n][0] *= corr_lo; oacc[n][1] *= corr_lo;
            oacc[n][2] *= corr_hi; oacc[n][3] *= corr_hi;
        }

        // --- Pack P accumulators -> A fragments ---
        uint32_t pf[4][4];
        #pragma unroll
        for (int k = 0; k < 4; k++) {
            pf[k][0] = packh2(sacc[2 * k][1],     sacc[2 * k][0]);
            pf[k][1] = packh2(sacc[2 * k][3],     sacc[2 * k][2]);
            pf[k][2] = packh2(sacc[2 * k + 1][1], sacc[2 * k + 1][0]);
            pf[k][3] = packh2(sacc[2 * k + 1][3], sacc[2 * k + 1][2]);
        }

        // --- GEMM2: O += P @ V ---
        {
            const uint32_t sV = smem_u32(Vc);
            const int vr  = (lane >> 3) * 8 + (lane & 7);
            const int vr2 = vr + 32;
            #pragma unroll
            for (int n = 0; n < 8; n++) {
                uint32_t vb[8];
                LDSM4T(vb[0], vb[1], vb[2], vb[3],
                       sV + vr * 128 + (((n ^ (vr & 7))) << 4));
                LDSM4T(vb[4], vb[5], vb[6], vb[7],
                       sV + vr2 * 128 + (((n ^ (vr2 & 7))) << 4));
                #pragma unroll
                for (int k = 0; k < 4; k++)
                    MMA16816(oacc[n], pf[k], vb[2 * k], vb[2 * k + 1]);
            }
        }
        __syncthreads();
    }

    // --- Epilogue ---
    const float inv_lo = 1.0f / lst[0];
    const float inv_hi = 1.0f / lst[1];
    #pragma unroll
    for (int n = 0; n < 8; n++) {
        const int col = h * HDd + n * 8 + 2 * t;
        float2 o0, o1;
        o0.x = oacc[n][0] * inv_lo; o0.y = oacc[n][1] * inv_lo;
        o1.x = oacc[n][2] * inv_hi; o1.y = oacc[n][3] * inv_hi;
        *(float2*)&Y[((size_t)(b * Tsz) + row_lo) * Csz + col] = o0;
        *(float2*)&Y[((size_t)(b * Tsz) + row_hi) * Csz + col] = o1;
    }
}

// ===========================================================================
extern "C" void kernel_launch(void* const* d_in, const int* in_sizes, int n_in,
                              void* d_out, int out_size) {
    (void)in_sizes; (void)n_in; (void)out_size;
    const float* x      = (const float*)d_in[0];
    const float* w_attn = (const float*)d_in[1];
    const float* b_attn = (const float*)d_in[2];
    const float* w_proj = (const float*)d_in[3];
    const float* b_proj = (const float*)d_in[4];
    float* out = (float*)d_out;

    float *p_qkv, *p_y;
    __half *p_qh, *p_kh, *p_vh;
    cudaGetSymbolAddress((void**)&p_qkv, g_qkv);
    cudaGetSymbolAddress((void**)&p_qh,  g_qh);
    cudaGetSymbolAddress((void**)&p_kh,  g_kh);
    cudaGetSymbolAddress((void**)&p_vh,  g_vh);
    cudaGetSymbolAddress((void**)&p_y,   g_y);

    const int M = Bsz * Tsz;

    sgemm128<<<dim3(3 * Csz / 128, M / 128), 256>>>(
        x, w_attn, b_attn, p_qkv, M, 3 * Csz, Csz);

    rope_split_kernel<<<(Bsz * Tsz * Hn * 32) / 256, 256>>>(p_qkv);

    flash_mma<<<dim3(Tsz / 128, Hn, Bsz), 256>>>(p_qh, p_kh, p_vh, p_y);

    sgemm128<<<dim3(Csz / 128, M / 128), 256>>>(
        p_y, w_proj, b_proj, out, M, Csz, Csz);
}

// round 7
// speedup vs baseline: 3.6051x; 3.6051x over previous
#include <cuda_runtime.h>
#include <cuda_fp16.h>
#include <math.h>
#include <stdint.h>

#define Bsz 2
#define Tsz 2048
#define Csz 1024
#define Hn  16
#define HDd 64

// Scratch (fp16 pipeline)
__device__ __half g_xh [Bsz * Tsz * Csz];
__device__ __half g_wah[Csz * 3 * Csz];
__device__ __half g_wph[Csz * Csz];
__device__ __half g_qkvh[Bsz * Tsz * 3 * Csz];
__device__ __half g_qh[Bsz * Hn * Tsz * HDd];
__device__ __half g_kh[Bsz * Hn * Tsz * HDd];
__device__ __half g_vh[Bsz * Hn * Tsz * HDd];
__device__ __half g_yh[Bsz * Tsz * Csz];

// ===========================================================================
// Helpers
// ===========================================================================
__device__ __forceinline__ uint32_t smem_u32(const void* p) {
    uint32_t a;
    asm("{ .reg .u64 t; cvta.to.shared.u64 t, %1; cvt.u32.u64 %0, t; }"
        : "=r"(a) : "l"(p));
    return a;
}

#define LDSM4(r0, r1, r2, r3, ad)                                              \
    asm volatile("ldmatrix.sync.aligned.m8n8.x4.shared.b16 {%0,%1,%2,%3}, [%4];" \
                 : "=r"(r0), "=r"(r1), "=r"(r2), "=r"(r3) : "r"(ad))

#define LDSM4T(r0, r1, r2, r3, ad)                                             \
    asm volatile("ldmatrix.sync.aligned.m8n8.x4.trans.shared.b16 {%0,%1,%2,%3}, [%4];" \
                 : "=r"(r0), "=r"(r1), "=r"(r2), "=r"(r3) : "r"(ad))

#define MMA16816(d, a, b0, b1)                                                 \
    asm volatile("mma.sync.aligned.m16n8k16.row.col.f32.f16.f16.f32 "          \
                 "{%0,%1,%2,%3}, {%4,%5,%6,%7}, {%8,%9}, {%0,%1,%2,%3};"       \
                 : "+f"((d)[0]), "+f"((d)[1]), "+f"((d)[2]), "+f"((d)[3])      \
                 : "r"((a)[0]), "r"((a)[1]), "r"((a)[2]), "r"((a)[3]),         \
                   "r"(b0), "r"(b1))

#define CP_ASYNC16(dst, src)                                                   \
    asm volatile("cp.async.cg.shared.global [%0], [%1], 16;"                   \
                 :: "r"(dst), "l"(src))
#define CP_COMMIT() asm volatile("cp.async.commit_group;" ::: "memory")
#define CP_WAIT1()  asm volatile("cp.async.wait_group 1;" ::: "memory")
#define CP_WAIT0()  asm volatile("cp.async.wait_group 0;" ::: "memory")

__device__ __forceinline__ float ex2f(float x) {
    float y;
    asm("ex2.approx.f32 %0, %1;" : "=f"(y) : "f"(x));
    return y;
}
__device__ __forceinline__ uint32_t packh2(float hi, float lo) {
    uint32_t r;
    asm("cvt.rn.f16x2.f32 %0, %1, %2;" : "=r"(r) : "f"(hi), "f"(lo));
    return r;
}

// ===========================================================================
// fp32 -> fp16 convert (vectorized)
// ===========================================================================
__global__ void f2h_kernel(const float* __restrict__ in,
                           __half* __restrict__ out, int n4) {
    const int i = blockIdx.x * blockDim.x + threadIdx.x;
    if (i < n4) {
        float4 v = ((const float4*)in)[i];
        ((__half2*)out)[2 * i]     = __floats2half2_rn(v.x, v.y);
        ((__half2*)out)[2 * i + 1] = __floats2half2_rn(v.z, v.w);
    }
}

// ===========================================================================
// HGEMM: C[M,N] = A[M,K](h) @ B[K,N](h) + bias(f32)
// 128x128 tile, BK=32, 8 warps (2M x 4N), warp tile 64x32, m16n8k16.
// cp.async double-buffered; swizzled smem; ldmatrix operand fetch.
// ===========================================================================
template <bool OUT_HALF>
__global__ __launch_bounds__(256)
void hgemm128(const __half* __restrict__ A, const __half* __restrict__ B,
              const float* __restrict__ bias, void* __restrict__ Cv,
              int M, int N, int K) {
    __shared__ char sm[49152];           // A: 2x16KB (128B rows), B: 2x8KB
    const uint32_t sAb = smem_u32(sm);
    const uint32_t sBb = smem_u32(sm + 32768);

    const int tid  = threadIdx.x;
    const int lane = tid & 31;
    const int wid  = tid >> 5;
    const int wm = wid >> 2;             // 0..1
    const int wn = wid & 3;              // 0..3
    const int m0 = blockIdx.y * 128;
    const int n0 = blockIdx.x * 128;
    const int NK = K >> 5;

    float acc[4][4][4] = {};

    // prologue: issue buffer 0
    {
        #pragma unroll
        for (int i = 0; i < 2; i++) {
            const int idx = tid + i * 256;
            const int ra = idx >> 2, ca = idx & 3;
            CP_ASYNC16(sAb + ra * 128 + ((ca ^ (ra & 7)) << 4),
                       A + (size_t)(m0 + ra) * K + ca * 8);
            const int rb = idx >> 4, cb = idx & 15;
            CP_ASYNC16(sBb + rb * 256 + ((cb ^ (rb & 7)) << 4),
                       B + (size_t)rb * N + n0 + cb * 8);
        }
        CP_COMMIT();
    }

    for (int it = 0; it < NK; it++) {
        if (it + 1 < NK) {
            const int buf = (it + 1) & 1;
            const int k0 = (it + 1) * 32;
            const uint32_t a0 = sAb + buf * 16384;
            const uint32_t b0 = sBb + buf * 8192;
            #pragma unroll
            for (int i = 0; i < 2; i++) {
                const int idx = tid + i * 256;
                const int ra = idx >> 2, ca = idx & 3;
                CP_ASYNC16(a0 + ra * 128 + ((ca ^ (ra & 7)) << 4),
                           A + (size_t)(m0 + ra) * K + k0 + ca * 8);
                const int rb = idx >> 4, cb = idx & 15;
                CP_ASYNC16(b0 + rb * 256 + ((cb ^ (rb & 7)) << 4),
                           B + (size_t)(k0 + rb) * N + n0 + cb * 8);
            }
            CP_COMMIT();
            CP_WAIT1();
        } else {
            CP_WAIT0();
        }
        __syncthreads();

        const uint32_t aB = sAb + (it & 1) * 16384;
        const uint32_t bB = sBb + (it & 1) * 8192;

        // B fragments: per n8 tile, k=0..31 via ldmatrix.x4.trans
        uint32_t vb[4][4];
        #pragma unroll
        for (int j = 0; j < 4; j++) {
            const int cn = wn * 4 + j;
            LDSM4T(vb[j][0], vb[j][1], vb[j][2], vb[j][3],
                   bB + lane * 256 + ((cn ^ (lane & 7)) << 4));
        }
        #pragma unroll
        for (int ks = 0; ks < 2; ks++) {
            uint32_t af[4][4];
            #pragma unroll
            for (int mt = 0; mt < 4; mt++) {
                const int row = wm * 64 + mt * 16 + (lane & 7) + ((lane >> 3) & 1) * 8;
                const int ch  = ks * 2 + (lane >> 4);
                LDSM4(af[mt][0], af[mt][1], af[mt][2], af[mt][3],
                      aB + row * 128 + ((ch ^ (row & 7)) << 4));
            }
            #pragma unroll
            for (int mt = 0; mt < 4; mt++)
                #pragma unroll
                for (int j = 0; j < 4; j++)
                    MMA16816(acc[mt][j], af[mt], vb[j][2 * ks], vb[j][2 * ks + 1]);
        }
        __syncthreads();
    }

    // epilogue
    #pragma unroll
    for (int mt = 0; mt < 4; mt++) {
        const int row_lo = m0 + wm * 64 + mt * 16 + (lane >> 2);
        const int row_hi = row_lo + 8;
        #pragma unroll
        for (int j = 0; j < 4; j++) {
            const int col = n0 + wn * 32 + j * 8 + (lane & 3) * 2;
            const float b0v = bias[col], b1v = bias[col + 1];
            if (OUT_HALF) {
                __half* C = (__half*)Cv;
                *(__half2*)&C[(size_t)row_lo * N + col] =
                    __floats2half2_rn(acc[mt][j][0] + b0v, acc[mt][j][1] + b1v);
                *(__half2*)&C[(size_t)row_hi * N + col] =
                    __floats2half2_rn(acc[mt][j][2] + b0v, acc[mt][j][3] + b1v);
            } else {
                float* C = (float*)Cv;
                float2 o0 = {acc[mt][j][0] + b0v, acc[mt][j][1] + b1v};
                float2 o1 = {acc[mt][j][2] + b0v, acc[mt][j][3] + b1v};
                *(float2*)&C[(size_t)row_lo * N + col] = o0;
                *(float2*)&C[(size_t)row_hi * N + col] = o1;
            }
        }
    }
}

// ===========================================================================
// RoPE + split + transpose (fp16 in/out)
// ===========================================================================
__global__ void rope_split_kernel(const __half* __restrict__ qkv) {
    const int idx = blockIdx.x * blockDim.x + threadIdx.x;
    const int d2 = idx & 31;
    const int h  = (idx >> 5) & 15;
    const int t  = (idx >> 9) & 2047;
    const int b  = idx >> 20;

    const __half* base = qkv + (size_t)(b * Tsz + t) * (3 * Csz);
    const int off = h * HDd + d2;

    const float qf = __half2float(base[off]);
    const float qs = __half2float(base[off + 32]);
    const float kf = __half2float(base[Csz + off]);
    const float ks = __half2float(base[Csz + off + 32]);
    const float vf = __half2float(base[2 * Csz + off]);
    const float vs = __half2float(base[2 * Csz + off + 32]);

    const float inv_ts = powf(10000.0f, -(float)d2 * (1.0f / 32.0f));
    const float ang = (float)t * inv_ts;
    float sn, cs;
    sincosf(ang, &sn, &cs);

    const size_t o = (size_t)((b * Hn + h) * Tsz + t) * HDd + d2;
    g_qh[o]      = __float2half_rn(qf * cs - qs * sn);
    g_qh[o + 32] = __float2half_rn(qs * cs + qf * sn);
    g_kh[o]      = __float2half_rn(kf * cs - ks * sn);
    g_kh[o + 32] = __float2half_rn(ks * cs + kf * sn);
    g_vh[o]      = __float2half_rn(vf);
    g_vh[o + 32] = __float2half_rn(vs);
}

// ===========================================================================
// Flash attention via mma.sync (fp16 in, fp32 accum), fp16 out.
// ===========================================================================
#define SCALE_L2E 0.1803368801111244f   // 0.125 * log2(e)

__global__ __launch_bounds__(256, 1)
void flash_mma(const __half* __restrict__ Q,
               const __half* __restrict__ K,
               const __half* __restrict__ V,
               __half* __restrict__ Y) {
    __shared__ char smem[49152];
    char* Qs = smem;                              // 16 KB
    char* Kb0 = smem + 16384;                     // 8 KB each
    char* Kb1 = smem + 24576;
    char* Vb0 = smem + 32768;
    char* Vb1 = smem + 40960;

    const int tid  = threadIdx.x;
    const int wid  = tid >> 5;
    const int lane = tid & 31;
    const int g = lane >> 2;
    const int t = lane & 3;

    const int qt = gridDim.x - 1 - blockIdx.x;
    const int h  = blockIdx.y;
    const int b  = blockIdx.z;
    const size_t bh = (size_t)(b * Hn + h) * Tsz;
    const int qbase = qt * 128 + wid * 16;
    const int row_lo = qbase + g;
    const int row_hi = row_lo + 8;

    #pragma unroll
    for (int i = 0; i < 4; i++) {
        const int idx = tid + i * 256;
        const int r = idx >> 3;
        const int c = idx & 7;
        uint4 q = *(const uint4*)&Q[(bh + qt * 128 + r) * HDd + c * 8];
        *(uint4*)(Qs + r * 128 + ((c ^ (r & 7)) << 4)) = q;
    }
    #pragma unroll
    for (int i = 0; i < 2; i++) {
        const int idx = tid + i * 256;
        const int r = idx >> 3;
        const int c = idx & 7;
        uint4 kk = *(const uint4*)&K[(bh + r) * HDd + c * 8];
        *(uint4*)(Kb0 + r * 128 + ((c ^ (r & 7)) << 4)) = kk;
        uint4 vv = *(const uint4*)&V[(bh + r) * HDd + c * 8];
        *(uint4*)(Vb0 + r * 128 + ((c ^ (r & 7)) << 4)) = vv;
    }
    __syncthreads();

    uint32_t qf[4][4];
    {
        const uint32_t sQ = smem_u32(Qs);
        const int mat = lane >> 3;
        const int qr  = wid * 16 + (lane & 7) + ((mat & 1) << 3);
        #pragma unroll
        for (int k = 0; k < 4; k++) {
            const int chunk = 2 * k + (mat >> 1);
            const uint32_t ad = sQ + qr * 128 + (((chunk ^ (qr & 7))) << 4);
            LDSM4(qf[k][0], qf[k][1], qf[k][2], qf[k][3], ad);
        }
    }

    float oacc[8][4] = {};
    float mst[2] = {-1e30f, -1e30f};
    float lst[2] = {0.0f, 0.0f};

    const int nkt = 2 * qt + 2;
    for (int kt = 0; kt < nkt; kt++) {
        char* Kc = (kt & 1) ? Kb1 : Kb0;
        char* Vc = (kt & 1) ? Vb1 : Vb0;

        if (kt + 1 < nkt) {
            char* Kn = (kt & 1) ? Kb0 : Kb1;
            char* Vn = (kt & 1) ? Vb0 : Vb1;
            const size_t base = bh + (size_t)(kt + 1) * 64;
            #pragma unroll
            for (int i = 0; i < 2; i++) {
                const int idx = tid + i * 256;
                const int r = idx >> 3;
                const int c = idx & 7;
                uint4 kk = *(const uint4*)&K[(base + r) * HDd + c * 8];
                *(uint4*)(Kn + r * 128 + ((c ^ (r & 7)) << 4)) = kk;
                uint4 vv = *(const uint4*)&V[(base + r) * HDd + c * 8];
                *(uint4*)(Vn + r * 128 + ((c ^ (r & 7)) << 4)) = vv;
            }
        }

        float sacc[8][4] = {};
        {
            const uint32_t sK = smem_u32(Kc);
            const int kr = lane & 7;
            #pragma unroll
            for (int n = 0; n < 8; n++) {
                const int row = n * 8 + kr;
                const int c0  = lane >> 3;
                uint32_t kb[8];
                const uint32_t rb = sK + row * 128;
                LDSM4(kb[0], kb[1], kb[2], kb[3],
                      rb + (((c0 ^ (row & 7))) << 4));
                LDSM4(kb[4], kb[5], kb[6], kb[7],
                      rb + ((((c0 + 4) ^ (row & 7))) << 4));
                #pragma unroll
                for (int k = 0; k < 4; k++)
                    MMA16816(sacc[n], qf[k], kb[2 * k], kb[2 * k + 1]);
            }
        }

        const bool dotest = (kt * 64 + 63) > qbase;
        float rmx_lo = -1e30f, rmx_hi = -1e30f;
        #pragma unroll
        for (int n = 0; n < 8; n++) {
            #pragma unroll
            for (int j = 0; j < 4; j++) sacc[n][j] *= SCALE_L2E;
            if (dotest) {
                const int cb = kt * 64 + n * 8 + 2 * t;
                if (cb     > row_lo) sacc[n][0] = -1e30f;
                if (cb + 1 > row_lo) sacc[n][1] = -1e30f;
                if (cb     > row_hi) sacc[n][2] = -1e30f;
                if (cb + 1 > row_hi) sacc[n][3] = -1e30f;
            }
            rmx_lo = fmaxf(rmx_lo, fmaxf(sacc[n][0], sacc[n][1]));
            rmx_hi = fmaxf(rmx_hi, fmaxf(sacc[n][2], sacc[n][3]));
        }
        rmx_lo = fmaxf(rmx_lo, __shfl_xor_sync(0xffffffffu, rmx_lo, 1));
        rmx_lo = fmaxf(rmx_lo, __shfl_xor_sync(0xffffffffu, rmx_lo, 2));
        rmx_hi = fmaxf(rmx_hi, __shfl_xor_sync(0xffffffffu, rmx_hi, 1));
        rmx_hi = fmaxf(rmx_hi, __shfl_xor_sync(0xffffffffu, rmx_hi, 2));

        const float mn_lo = fmaxf(mst[0], rmx_lo);
        const float mn_hi = fmaxf(mst[1], rmx_hi);
        const float corr_lo = ex2f(mst[0] - mn_lo);
        const float corr_hi = ex2f(mst[1] - mn_hi);
        mst[0] = mn_lo; mst[1] = mn_hi;

        float sum_lo = 0.0f, sum_hi = 0.0f;
        #pragma unroll
        for (int n = 0; n < 8; n++) {
            sacc[n][0] = ex2f(sacc[n][0] - mn_lo);
            sacc[n][1] = ex2f(sacc[n][1] - mn_lo);
            sacc[n][2] = ex2f(sacc[n][2] - mn_hi);
            sacc[n][3] = ex2f(sacc[n][3] - mn_hi);
            sum_lo += sacc[n][0] + sacc[n][1];
            sum_hi += sacc[n][2] + sacc[n][3];
        }
        sum_lo += __shfl_xor_sync(0xffffffffu, sum_lo, 1);
        sum_lo += __shfl_xor_sync(0xffffffffu, sum_lo, 2);
        sum_hi += __shfl_xor_sync(0xffffffffu, sum_hi, 1);
        sum_hi += __shfl_xor_sync(0xffffffffu, sum_hi, 2);
        lst[0] = lst[0] * corr_lo + sum_lo;
        lst[1] = lst[1] * corr_hi + sum_hi;

        #pragma unroll
        for (int n = 0; n < 8; n++) {
            oacc[n][0] *= corr_lo; oacc[n][1] *= corr_lo;
            oacc[n][2] *= corr_hi; oacc[n][3] *= corr_hi;
        }

        uint32_t pf[4][4];
        #pragma unroll
        for (int k = 0; k < 4; k++) {
            pf[k][0] = packh2(sacc[2 * k][1],     sacc[2 * k][0]);
            pf[k][1] = packh2(sacc[2 * k][3],     sacc[2 * k][2]);
            pf[k][2] = packh2(sacc[2 * k + 1][1], sacc[2 * k + 1][0]);
            pf[k][3] = packh2(sacc[2 * k + 1][3], sacc[2 * k + 1][2]);
        }

        {
            const uint32_t sV = smem_u32(Vc);
            const int vr  = (lane >> 3) * 8 + (lane & 7);
            const int vr2 = vr + 32;
            #pragma unroll
            for (int n = 0; n < 8; n++) {
                uint32_t vb[8];
                LDSM4T(vb[0], vb[1], vb[2], vb[3],
                       sV + vr * 128 + (((n ^ (vr & 7))) << 4));
                LDSM4T(vb[4], vb[5], vb[6], vb[7],
                       sV + vr2 * 128 + (((n ^ (vr2 & 7))) << 4));
                #pragma unroll
                for (int k = 0; k < 4; k++)
                    MMA16816(oacc[n], pf[k], vb[2 * k], vb[2 * k + 1]);
            }
        }
        __syncthreads();
    }

    const float inv_lo = 1.0f / lst[0];
    const float inv_hi = 1.0f / lst[1];
    #pragma unroll
    for (int n = 0; n < 8; n++) {
        const int col = h * HDd + n * 8 + 2 * t;
        *(__half2*)&Y[((size_t)(b * Tsz) + row_lo) * Csz + col] =
            __floats2half2_rn(oacc[n][0] * inv_lo, oacc[n][1] * inv_lo);
        *(__half2*)&Y[((size_t)(b * Tsz) + row_hi) * Csz + col] =
            __floats2half2_rn(oacc[n][2] * inv_hi, oacc[n][3] * inv_hi);
    }
}

// ===========================================================================
extern "C" void kernel_launch(void* const* d_in, const int* in_sizes, int n_in,
                              void* d_out, int out_size) {
    (void)in_sizes; (void)n_in; (void)out_size;
    const float* x      = (const float*)d_in[0];
    const float* w_attn = (const float*)d_in[1];
    const float* b_attn = (const float*)d_in[2];
    const float* w_proj = (const float*)d_in[3];
    const float* b_proj = (const float*)d_in[4];
    float* out = (float*)d_out;

    __half *p_xh, *p_wah, *p_wph, *p_qkvh, *p_qh, *p_kh, *p_vh, *p_yh;
    cudaGetSymbolAddress((void**)&p_xh,   g_xh);
    cudaGetSymbolAddress((void**)&p_wah,  g_wah);
    cudaGetSymbolAddress((void**)&p_wph,  g_wph);
    cudaGetSymbolAddress((void**)&p_qkvh, g_qkvh);
    cudaGetSymbolAddress((void**)&p_qh,   g_qh);
    cudaGetSymbolAddress((void**)&p_kh,   g_kh);
    cudaGetSymbolAddress((void**)&p_vh,   g_vh);
    cudaGetSymbolAddress((void**)&p_yh,   g_yh);

    const int M = Bsz * Tsz;  // 4096

    // 0) fp32 -> fp16 converts
    f2h_kernel<<<(M * Csz / 4) / 256, 256>>>(x, p_xh, M * Csz / 4);
    f2h_kernel<<<(Csz * 3 * Csz / 4) / 256, 256>>>(w_attn, p_wah, Csz * 3 * Csz / 4);
    f2h_kernel<<<(Csz * Csz / 4) / 256, 256>>>(w_proj, p_wph, Csz * Csz / 4);

    // 1) QKV = x @ w_attn + b_attn   (fp16 out)
    hgemm128<true><<<dim3(3 * Csz / 128, M / 128), 256>>>(
        p_xh, p_wah, b_attn, p_qkvh, M, 3 * Csz, Csz);

    // 2) RoPE + split
    rope_split_kernel<<<(Bsz * Tsz * Hn * 32) / 256, 256>>>(p_qkvh);

    // 3) Flash attention (fp16 out)
    flash_mma<<<dim3(Tsz / 128, Hn, Bsz), 256>>>(p_qh, p_kh, p_vh, p_yh);

    // 4) out = y @ w_proj + b_proj   (fp32 out)
    hgemm128<false><<<dim3(Csz / 128, M / 128), 256>>>(
        p_yh, p_wph, b_proj, out, M, Csz, Csz);
}